// round 4
// baseline (speedup 1.0000x reference)
#include <cuda_runtime.h>

// Problem constants
#define NB   8      // batch
#define NC   512    // input channels
#define NHW  9216   // H*W = 96*96
#define NO   256    // output channels
#define NL   19     // labels
#define LP   20     // padded labels
#define EPSV 1e-5f

// ---------------- scratch (device globals; no allocation allowed) ----------
__device__ float g_q1[NB * NO * NHW];            // 75.5 MB intermediate q1
__device__ float g_ctx_part[32 * NB * NC * LP];  // 10.5 MB context partials
__device__ float g_ctx[NB * NC * LP];            // [B][C][LP], LP-padded (col 19 = 0)
__device__ float g_k1[NB * LP * NO];             // [B][LP][O]
__device__ float g_key[NB * NO * LP];            // [B][O][LP]
__device__ float g_val[NB * NO * LP];            // [B][O][LP]
__device__ float g_scale[5 * NO];                // folded BN scale: q1,q2,k1,k2,v
__device__ float g_bias[5 * NO];                 // folded BN bias

// ---------------- prep: fold BN into per-channel scale/bias ----------------
__global__ void prep_kernel(const float* __restrict__ bnq1, const float* __restrict__ bnq2,
                            const float* __restrict__ bnk1, const float* __restrict__ bnk2,
                            const float* __restrict__ bnv) {
    int t = blockIdx.x * 256 + threadIdx.x;
    if (t >= 5 * NO) return;
    const float* bn;
    switch (t >> 8) {
        case 0: bn = bnq1; break;
        case 1: bn = bnq2; break;
        case 2: bn = bnk1; break;
        case 3: bn = bnk2; break;
        default: bn = bnv; break;
    }
    int o = t & 255;
    float g = bn[o], be = bn[NO + o], mm = bn[2 * NO + o], vv = bn[3 * NO + o];
    float s = g * rsqrtf(vv + EPSV);
    g_scale[t] = s;
    g_bias[t]  = be - mm * s;
}

// ---------------- context: ctx[b,c,l] = sum_h aux[b,l,h] * sf[b,c,h] -------
// grid (8 hsplit, 8 ctile, B), 256 threads. Writes 32 partial sums (no atomics
// -> bitwise deterministic), reduced by ctx_reduce_kernel.
#define CTILE  64
#define CHUNK  32
#define HSPLIT 8
__global__ void __launch_bounds__(256)
context_kernel(const float* __restrict__ sf, const float* __restrict__ aux) {
    __shared__ float sf_s[CHUNK][CTILE + 4];  // [h][c], row stride 68 (16B aligned)
    __shared__ float aux_s[LP][CHUNK];        // [l][h]

    const int b  = blockIdx.z;
    const int c0 = blockIdx.y * CTILE;
    const int hbase = blockIdx.x * (NHW / HSPLIT);  // 1152-wide h range

    const int t    = threadIdx.x;
    const int tx   = t & 15;          // 4 c's: c = c0 + tx*4 + ci
    const int lgrp = (t >> 4) & 3;    // 5 l's: l = lgrp*5 + lj
    const int hs   = t >> 6;          // 4 h-subslices within each chunk

    float acc[4][5];
#pragma unroll
    for (int i = 0; i < 4; ++i)
#pragma unroll
        for (int j = 0; j < 5; ++j) acc[i][j] = 0.f;

    const float* sfb  = sf  + (size_t)b * NC * NHW;
    const float* auxb = aux + (size_t)b * NL * NHW;

    for (int h0 = hbase; h0 < hbase + NHW / HSPLIT; h0 += CHUNK) {
        // load sf tile [32 h][64 c] (coalesced along h)
#pragma unroll
        for (int i = 0; i < (CTILE * CHUNK) / 256; ++i) {
            int e = t + i * 256;
            int ci = e >> 5, hi = e & 31;
            sf_s[hi][ci] = sfb[(size_t)(c0 + ci) * NHW + h0 + hi];
        }
        // load aux tile [20 l][32 h], pad l=19 with zeros
        for (int e = t; e < LP * CHUNK; e += 256) {
            int li = e >> 5, hi = e & 31;
            aux_s[li][hi] = (li < NL) ? auxb[(size_t)li * NHW + h0 + hi] : 0.f;
        }
        __syncthreads();
#pragma unroll
        for (int hh = 0; hh < 8; ++hh) {
            int h = hs * 8 + hh;
            float4 s4 = *(const float4*)&sf_s[h][tx * 4];
            float sv[4] = {s4.x, s4.y, s4.z, s4.w};
#pragma unroll
            for (int lj = 0; lj < 5; ++lj) {
                float av = aux_s[lgrp * 5 + lj][h];
#pragma unroll
                for (int ci = 0; ci < 4; ++ci)
                    acc[ci][lj] = fmaf(sv[ci], av, acc[ci][lj]);
            }
        }
        __syncthreads();
    }

    const int pidx = blockIdx.x * 4 + hs;  // 0..31
    float* dst = g_ctx_part + (size_t)pidx * (NB * NC * LP);
#pragma unroll
    for (int ci = 0; ci < 4; ++ci)
#pragma unroll
        for (int lj = 0; lj < 5; ++lj)
            dst[((size_t)b * NC + c0 + tx * 4 + ci) * LP + lgrp * 5 + lj] = acc[ci][lj];
}

__global__ void ctx_reduce_kernel() {
    int i = blockIdx.x * 256 + threadIdx.x;
    if (i >= NB * NC * LP) return;
    float s = 0.f;
#pragma unroll
    for (int p = 0; p < 32; ++p) s += g_ctx_part[(size_t)p * (NB * NC * LP) + i];
    g_ctx[i] = s;
}

// ---------------- kv stage A: k1 = relu(BN(Wk1 @ ctx)), v = relu(BN(Wv @ ctx))
// grid (2 which, 8 otile, B), 160 threads (5 warps). warp w -> l-group w*4..w*4+3,
// lane -> output row o. ctx broadcast from shared; W rows served by L1.
__global__ void __launch_bounds__(160)
kv_a_kernel(const float* __restrict__ Wk1, const float* __restrict__ Wv) {
    __shared__ float ctx_s[LP][NC];  // [l][c] transposed, 40KB

    const int b  = blockIdx.z;
    const int o0 = blockIdx.y * 32;
    const int which = blockIdx.x;  // 0 -> k1, 1 -> v
    const int t = threadIdx.x;

    for (int e = t; e < NC * LP; e += 160) {
        int c = e / LP, l = e % LP;
        ctx_s[l][c] = g_ctx[(size_t)b * NC * LP + e];
    }
    __syncthreads();

    const float* Wm = which ? Wv : Wk1;
    const int sidx  = which ? 4 : 2;

    const int w    = t >> 5;       // warp 0..4 -> l base
    const int lane = t & 31;
    const int lb   = w * 4;
    const int o    = o0 + lane;

    float acc[4] = {0.f, 0.f, 0.f, 0.f};
    for (int c4 = 0; c4 < NC; c4 += 4) {
        float4 w4 = *(const float4*)&Wm[(size_t)o * NC + c4];
#pragma unroll
        for (int lj = 0; lj < 4; ++lj) {
            float4 x4 = *(const float4*)&ctx_s[lb + lj][c4];
            acc[lj] += w4.x * x4.x + w4.y * x4.y + w4.z * x4.z + w4.w * x4.w;
        }
    }
    float s  = g_scale[sidx * NO + o];
    float bi = g_bias[sidx * NO + o];
#pragma unroll
    for (int lj = 0; lj < 4; ++lj) {
        float y = fmaxf(fmaf(acc[lj], s, bi), 0.f);
        if (which == 0)
            g_k1[((size_t)b * LP + lb + lj) * NO + o] = y;   // [B][LP][O]
        else
            g_val[((size_t)b * NO + o) * LP + lb + lj] = y;  // [B][O][LP]
    }
}

// ---------------- kv stage B: key = relu(BN(Wk2 @ k1)) ---------------------
// grid (8 otile, B), 160 threads.
__global__ void __launch_bounds__(160)
kv_b_kernel(const float* __restrict__ Wk2) {
    __shared__ float k1_s[LP][NO];  // 20KB

    const int b  = blockIdx.y;
    const int o0 = blockIdx.x * 32;
    const int t = threadIdx.x;

    for (int e = t; e < LP * NO; e += 160)
        ((float*)k1_s)[e] = g_k1[(size_t)b * LP * NO + e];
    __syncthreads();

    const int w    = t >> 5;
    const int lane = t & 31;
    const int lb   = w * 4;
    const int o    = o0 + lane;

    float acc[4] = {0.f, 0.f, 0.f, 0.f};
    for (int c4 = 0; c4 < NO; c4 += 4) {
        float4 w4 = *(const float4*)&Wk2[(size_t)o * NO + c4];
#pragma unroll
        for (int lj = 0; lj < 4; ++lj) {
            float4 x4 = *(const float4*)&k1_s[lb + lj][c4];
            acc[lj] += w4.x * x4.x + w4.y * x4.y + w4.z * x4.z + w4.w * x4.w;
        }
    }
    float s  = g_scale[3 * NO + o];
    float bi = g_bias[3 * NO + o];
#pragma unroll
    for (int lj = 0; lj < 4; ++lj)
        g_key[((size_t)b * NO + o) * LP + lb + lj] = fmaxf(fmaf(acc[lj], s, bi), 0.f);
}

// ---------------- big GEMM: Y[b] = relu(W[M,K] @ X[b][K,NHW] * s + bias) ----
// M = 256 fixed. 128x128x8 tiles, 256 threads, 8x8 micro-tile, double-buffered.
__global__ void __launch_bounds__(256, 2)
gemm_bias_relu(const float* __restrict__ Wm, const float* __restrict__ Xext,
               float* Yext, int K, int sidx, int src_internal, int dst_internal) {
    __shared__ float As[2][8][128];
    __shared__ float Bs[2][8][128];

    const float* X = src_internal ? g_q1 : Xext;
    float*       Y = dst_internal ? g_q1 : Yext;

    const int t  = threadIdx.x;
    const int b  = blockIdx.z;
    const int m0 = blockIdx.y * 128;
    const int n0 = blockIdx.x * 128;

    const float* Xb = X + (size_t)b * K * NHW;
    float*       Yb = Y + (size_t)b * NO * NHW;

    const int aRow = t >> 1;            // 0..127
    const int aK4  = (t & 1) << 2;      // 0 or 4
    const int bRow = t >> 5;            // 0..7
    const int bC   = (t & 31) << 2;     // 0..124
    const int ty   = t >> 4;            // 0..15
    const int tx   = t & 15;            // 0..15

    float acc[8][8];
#pragma unroll
    for (int i = 0; i < 8; ++i)
#pragma unroll
        for (int j = 0; j < 8; ++j) acc[i][j] = 0.f;

    float4 pa = *(const float4*)(Wm + (size_t)(m0 + aRow) * K + aK4);
    float4 pb = *(const float4*)(Xb + (size_t)bRow * NHW + n0 + bC);

    int buf = 0;
    As[0][aK4 + 0][aRow] = pa.x;
    As[0][aK4 + 1][aRow] = pa.y;
    As[0][aK4 + 2][aRow] = pa.z;
    As[0][aK4 + 3][aRow] = pa.w;
    *(float4*)(&Bs[0][bRow][bC]) = pb;
    __syncthreads();

    const int ktiles = K >> 3;
    for (int kt = 0; kt < ktiles; ++kt) {
        if (kt + 1 < ktiles) {
            pa = *(const float4*)(Wm + (size_t)(m0 + aRow) * K + (kt + 1) * 8 + aK4);
            pb = *(const float4*)(Xb + (size_t)((kt + 1) * 8 + bRow) * NHW + n0 + bC);
        }
#pragma unroll
        for (int k = 0; k < 8; ++k) {
            float a0[8], b0[8];
            *(float4*)&a0[0] = *(const float4*)&As[buf][k][ty * 8];
            *(float4*)&a0[4] = *(const float4*)&As[buf][k][ty * 8 + 4];
            *(float4*)&b0[0] = *(const float4*)&Bs[buf][k][tx * 8];
            *(float4*)&b0[4] = *(const float4*)&Bs[buf][k][tx * 8 + 4];
#pragma unroll
            for (int i = 0; i < 8; ++i)
#pragma unroll
                for (int j = 0; j < 8; ++j)
                    acc[i][j] = fmaf(a0[i], b0[j], acc[i][j]);
        }
        if (kt + 1 < ktiles) {
            buf ^= 1;
            As[buf][aK4 + 0][aRow] = pa.x;
            As[buf][aK4 + 1][aRow] = pa.y;
            As[buf][aK4 + 2][aRow] = pa.z;
            As[buf][aK4 + 3][aRow] = pa.w;
            *(float4*)(&Bs[buf][bRow][bC]) = pb;
            __syncthreads();
        }
    }

#pragma unroll
    for (int i = 0; i < 8; ++i) {
        int m = m0 + ty * 8 + i;
        float sc = g_scale[sidx * NO + m];
        float bi = g_bias[sidx * NO + m];
        float4 r0, r1;
        r0.x = fmaxf(fmaf(acc[i][0], sc, bi), 0.f);
        r0.y = fmaxf(fmaf(acc[i][1], sc, bi), 0.f);
        r0.z = fmaxf(fmaf(acc[i][2], sc, bi), 0.f);
        r0.w = fmaxf(fmaf(acc[i][3], sc, bi), 0.f);
        r1.x = fmaxf(fmaf(acc[i][4], sc, bi), 0.f);
        r1.y = fmaxf(fmaf(acc[i][5], sc, bi), 0.f);
        r1.z = fmaxf(fmaf(acc[i][6], sc, bi), 0.f);
        r1.w = fmaxf(fmaf(acc[i][7], sc, bi), 0.f);
        *(float4*)(Yb + (size_t)m * NHW + n0 + tx * 8)     = r0;
        *(float4*)(Yb + (size_t)m * NHW + n0 + tx * 8 + 4) = r1;
    }
}

// ---------------- attention: per-pixel softmax over L=19 -------------------
// q lives in d_out ([B][O][HW]); each thread owns one pixel column; reads all
// q[o][n] first, then overwrites out[o][n] — alias-safe within the thread.
__global__ void __launch_bounds__(256)
attention_kernel(float* qout) {
    __shared__ float key_s[NO * LP];
    __shared__ float val_s[NO * LP];

    const int b = blockIdx.y;
    const int t = threadIdx.x;
    const int n = blockIdx.x * 256 + t;

    for (int e = t; e < NO * LP; e += 256) {
        key_s[e] = g_key[(size_t)b * NO * LP + e];
        val_s[e] = g_val[(size_t)b * NO * LP + e];
    }
    __syncthreads();

    float s[LP];
#pragma unroll
    for (int l = 0; l < LP; ++l) s[l] = 0.f;

    float* qb = qout + (size_t)b * NO * NHW + n;
#pragma unroll 4
    for (int o = 0; o < NO; ++o) {
        float qv = qb[(size_t)o * NHW];
#pragma unroll
        for (int j = 0; j < 5; ++j) {
            float4 k4 = *(const float4*)&key_s[o * LP + j * 4];
            s[j * 4 + 0] = fmaf(qv, k4.x, s[j * 4 + 0]);
            s[j * 4 + 1] = fmaf(qv, k4.y, s[j * 4 + 1]);
            s[j * 4 + 2] = fmaf(qv, k4.z, s[j * 4 + 2]);
            s[j * 4 + 3] = fmaf(qv, k4.w, s[j * 4 + 3]);
        }
    }

    // softmax over the 19 valid labels (scale 1/sqrt(256) = 0.0625)
    float mx = -1e30f;
#pragma unroll
    for (int l = 0; l < NL; ++l) {
        s[l] *= 0.0625f;
        mx = fmaxf(mx, s[l]);
    }
    float sum = 0.f;
#pragma unroll
    for (int l = 0; l < NL; ++l) {
        s[l] = __expf(s[l] - mx);
        sum += s[l];
    }
    float inv = 1.f / sum;
#pragma unroll
    for (int l = 0; l < NL; ++l) s[l] *= inv;
    s[19] = 0.f;  // padded label contributes nothing

#pragma unroll 4
    for (int o = 0; o < NO; ++o) {
        float acc = 0.f;
#pragma unroll
        for (int j = 0; j < 5; ++j) {
            float4 v4 = *(const float4*)&val_s[o * LP + j * 4];
            acc = fmaf(s[j * 4 + 0], v4.x, acc);
            acc = fmaf(s[j * 4 + 1], v4.y, acc);
            acc = fmaf(s[j * 4 + 2], v4.z, acc);
            acc = fmaf(s[j * 4 + 3], v4.w, acc);
        }
        qb[(size_t)o * NHW] = acc;
    }
}

// ---------------- launch ---------------------------------------------------
extern "C" void kernel_launch(void* const* d_in, const int* in_sizes, int n_in,
                              void* d_out, int out_size) {
    const float* tfeat = (const float*)d_in[0];   // target_task_feats [B,C,H,W]
    const float* sfeat = (const float*)d_in[1];   // source_task_feats [B,C,H,W]
    const float* taux  = (const float*)d_in[2];   // target_aux_prob   [B,L,HW]
    // d_in[3] = source_aux_prob (unused by reference)
    const float* Wq1  = (const float*)d_in[4];
    const float* bnq1 = (const float*)d_in[5];
    const float* Wq2  = (const float*)d_in[6];
    const float* bnq2 = (const float*)d_in[7];
    const float* Wk1  = (const float*)d_in[8];
    const float* bnk1 = (const float*)d_in[9];
    const float* Wk2  = (const float*)d_in[10];
    const float* bnk2 = (const float*)d_in[11];
    const float* Wv   = (const float*)d_in[12];
    const float* bnv  = (const float*)d_in[13];
    float* out = (float*)d_out;

    // 1. fold BN params
    prep_kernel<<<5, 256>>>(bnq1, bnq2, bnk1, bnk2, bnv);

    // 2. context = aux^T @ source feats (partials), then reduce
    context_kernel<<<dim3(HSPLIT, NC / CTILE, NB), 256>>>(sfeat, taux);
    ctx_reduce_kernel<<<(NB * NC * LP + 255) / 256, 256>>>();

    // 3. key / value small convs
    kv_a_kernel<<<dim3(2, NO / 32, NB), 160>>>(Wk1, Wv);
    kv_b_kernel<<<dim3(NO / 32, NB), 160>>>(Wk2);

    // 4. query GEMMs: q1 = relu(BN(Wq1@x)) -> g_q1 ; q = relu(BN(Wq2@q1)) -> d_out
    gemm_bias_relu<<<dim3(NHW / 128, NO / 128, NB), 256>>>(Wq1, tfeat, nullptr, NC, 0, 0, 1);
    gemm_bias_relu<<<dim3(NHW / 128, NO / 128, NB), 256>>>(Wq2, nullptr, out, NO, 1, 1, 0);

    // 5. attention (reads q from d_out, writes out to d_out in place)
    attention_kernel<<<dim3(NHW / 256, NB), 256>>>(out);
}

// round 7
// speedup vs baseline: 1.4998x; 1.4998x over previous
#include <cuda_runtime.h>
#include <cuda_bf16.h>
#include <stdint.h>

// Problem constants
#define NB   8      // batch
#define NC   512    // input channels
#define NHW  9216   // H*W = 96*96
#define NO   256    // output channels
#define NL   19     // labels
#define LP   20     // padded labels
#define EPSV 1e-5f

// ---------------- scratch (device globals; no allocation allowed) ----------
__device__ __nv_bfloat16 g_xh[NB * NC * NHW];    // 72MB  bf16 hi of target feats
__device__ __nv_bfloat16 g_xl[NB * NC * NHW];    // 72MB  bf16 lo
__device__ __nv_bfloat16 g_q1h[NB * NO * NHW];   // 36MB  bf16 hi of q1
__device__ __nv_bfloat16 g_q1l[NB * NO * NHW];   // 36MB  bf16 lo
__device__ float g_ctx_part[32 * NB * NC * LP];  // 10.5MB context partials
__device__ float g_ctx_t[NB * LP * NC];          // [B][LP][C] transposed context
__device__ float g_k1[NB * LP * NO];             // [B][LP][O]
__device__ float g_key[NB * NO * LP];            // [B][O][LP]
__device__ float g_val[NB * NO * LP];            // [B][O][LP]
__device__ float g_scale[5 * NO];                // folded BN scale: q1,q2,k1,k2,v
__device__ float g_bias[5 * NO];                 // folded BN bias
__device__ __nv_bfloat16 g_w1h[NO * NC];         // bf16 splits of Wq1 / Wq2
__device__ __nv_bfloat16 g_w1l[NO * NC];
__device__ __nv_bfloat16 g_w2h[NO * NO];
__device__ __nv_bfloat16 g_w2l[NO * NO];

// ======================= PTX helpers (plain ISA, no 'a' features) ==========
__device__ __forceinline__ uint32_t smem_u32(const void* p) {
    uint32_t a;
    asm("{ .reg .u64 t; cvta.to.shared.u64 t, %1; cvt.u32.u64 %0, t; }" : "=r"(a) : "l"(p));
    return a;
}
__device__ __forceinline__ void cpa16(uint32_t dst, const void* src) {
    asm volatile("cp.async.cg.shared.global [%0], [%1], 16;" :: "r"(dst), "l"(src));
}
#define CP_COMMIT() asm volatile("cp.async.commit_group;" ::: "memory")
#define CP_WAIT2()  asm volatile("cp.async.wait_group 2;" ::: "memory")

__device__ __forceinline__ void ldsm4(uint32_t* r, uint32_t addr) {
    asm volatile("ldmatrix.sync.aligned.m8n8.x4.shared.b16 {%0,%1,%2,%3}, [%4];"
        : "=r"(r[0]), "=r"(r[1]), "=r"(r[2]), "=r"(r[3]) : "r"(addr));
}
__device__ __forceinline__ void ldsm4t(uint32_t* r, uint32_t addr) {
    asm volatile("ldmatrix.sync.aligned.m8n8.x4.trans.shared.b16 {%0,%1,%2,%3}, [%4];"
        : "=r"(r[0]), "=r"(r[1]), "=r"(r[2]), "=r"(r[3]) : "r"(addr));
}
__device__ __forceinline__ void mma_bf16(float* d, const uint32_t* a, uint32_t b0, uint32_t b1) {
    asm volatile(
        "mma.sync.aligned.m16n8k16.row.col.f32.bf16.bf16.f32 "
        "{%0,%1,%2,%3}, {%4,%5,%6,%7}, {%8,%9}, {%0,%1,%2,%3};"
        : "+f"(d[0]), "+f"(d[1]), "+f"(d[2]), "+f"(d[3])
        : "r"(a[0]), "r"(a[1]), "r"(a[2]), "r"(a[3]), "r"(b0), "r"(b1));
}

// ---------------- prep: fold BN into per-channel scale/bias ----------------
__global__ void prep_kernel(const float* __restrict__ bnq1, const float* __restrict__ bnq2,
                            const float* __restrict__ bnk1, const float* __restrict__ bnk2,
                            const float* __restrict__ bnv) {
    int t = blockIdx.x * 256 + threadIdx.x;
    if (t >= 5 * NO) return;
    const float* bn;
    switch (t >> 8) {
        case 0: bn = bnq1; break;
        case 1: bn = bnq2; break;
        case 2: bn = bnk1; break;
        case 3: bn = bnk2; break;
        default: bn = bnv; break;
    }
    int o = t & 255;
    float g = bn[o], be = bn[NO + o], mm = bn[2 * NO + o], vv = bn[3 * NO + o];
    float s = g * rsqrtf(vv + EPSV);
    g_scale[t] = s;
    g_bias[t]  = be - mm * s;
}

// ---------------- prep: bf16 hi/lo split of Wq1, Wq2 -----------------------
__global__ void wsplit_kernel(const float* __restrict__ Wq1, const float* __restrict__ Wq2) {
    int t = blockIdx.x * 256 + threadIdx.x;
    if (t < NO * NC) {
        float x = Wq1[t];
        __nv_bfloat16 h = __float2bfloat16(x);
        g_w1h[t] = h;
        g_w1l[t] = __float2bfloat16(x - __bfloat162float(h));
    }
    int u = t - NO * NC;
    if (u >= 0 && u < NO * NO) {
        float x = Wq2[u];
        __nv_bfloat16 h = __float2bfloat16(x);
        g_w2h[u] = h;
        g_w2l[u] = __float2bfloat16(x - __bfloat162float(h));
    }
}

// ---------------- prep: bf16 hi/lo split of target feats -------------------
__global__ void __launch_bounds__(256)
xsplit_kernel(const float* __restrict__ x) {
    size_t i = (size_t)blockIdx.x * 256 + threadIdx.x;  // float4 index
    if (i >= (size_t)NB * NC * NHW / 4) return;
    float4 v = ((const float4*)x)[i];
    float xv[4] = {v.x, v.y, v.z, v.w};
    __nv_bfloat16 h[4], l[4];
#pragma unroll
    for (int j = 0; j < 4; ++j) {
        h[j] = __float2bfloat16(xv[j]);
        l[j] = __float2bfloat16(xv[j] - __bfloat162float(h[j]));
    }
    __nv_bfloat162* ph = (__nv_bfloat162*)g_xh;
    __nv_bfloat162* pl = (__nv_bfloat162*)g_xl;
    __nv_bfloat162 a, b;
    a.x = h[0]; a.y = h[1]; b.x = h[2]; b.y = h[3];
    ph[i * 2] = a; ph[i * 2 + 1] = b;
    a.x = l[0]; a.y = l[1]; b.x = l[2]; b.y = l[3];
    pl[i * 2] = a; pl[i * 2 + 1] = b;
}

// ---------------- context: ctx[b,c,l] = sum_h aux[b,l,h] * sf[b,c,h] -------
#define CTILE  64
#define CHUNK  32
#define HSPLIT 8
__global__ void __launch_bounds__(256)
context_kernel(const float* __restrict__ sf, const float* __restrict__ aux) {
    __shared__ float sf_s[CHUNK][CTILE + 4];
    __shared__ float aux_s[LP][CHUNK];

    const int b  = blockIdx.z;
    const int c0 = blockIdx.y * CTILE;
    const int hbase = blockIdx.x * (NHW / HSPLIT);

    const int t    = threadIdx.x;
    const int tx   = t & 15;
    const int lgrp = (t >> 4) & 3;
    const int hs   = t >> 6;

    float acc[4][5];
#pragma unroll
    for (int i = 0; i < 4; ++i)
#pragma unroll
        for (int j = 0; j < 5; ++j) acc[i][j] = 0.f;

    const float* sfb  = sf  + (size_t)b * NC * NHW;
    const float* auxb = aux + (size_t)b * NL * NHW;

    for (int h0 = hbase; h0 < hbase + NHW / HSPLIT; h0 += CHUNK) {
#pragma unroll
        for (int i = 0; i < (CTILE * CHUNK) / 256; ++i) {
            int e = t + i * 256;
            int ci = e >> 5, hi = e & 31;
            sf_s[hi][ci] = sfb[(size_t)(c0 + ci) * NHW + h0 + hi];
        }
        for (int e = t; e < LP * CHUNK; e += 256) {
            int li = e >> 5, hi = e & 31;
            aux_s[li][hi] = (li < NL) ? auxb[(size_t)li * NHW + h0 + hi] : 0.f;
        }
        __syncthreads();
#pragma unroll
        for (int hh = 0; hh < 8; ++hh) {
            int h = hs * 8 + hh;
            float4 s4 = *(const float4*)&sf_s[h][tx * 4];
            float sv[4] = {s4.x, s4.y, s4.z, s4.w};
#pragma unroll
            for (int lj = 0; lj < 5; ++lj) {
                float av = aux_s[lgrp * 5 + lj][h];
#pragma unroll
                for (int ci = 0; ci < 4; ++ci)
                    acc[ci][lj] = fmaf(sv[ci], av, acc[ci][lj]);
            }
        }
        __syncthreads();
    }

    const int pidx = blockIdx.x * 4 + hs;
    float* dst = g_ctx_part + (size_t)pidx * (NB * NC * LP);
#pragma unroll
    for (int ci = 0; ci < 4; ++ci)
#pragma unroll
        for (int lj = 0; lj < 5; ++lj)
            dst[((size_t)b * NC + c0 + tx * 4 + ci) * LP + lgrp * 5 + lj] = acc[ci][lj];
}

// reduce 32 partials; write TRANSPOSED ctx_t[b][l][c]
__global__ void ctx_reduce_kernel() {
    int i = blockIdx.x * 256 + threadIdx.x;
    if (i >= NB * NC * LP) return;
    float s = 0.f;
#pragma unroll
    for (int p = 0; p < 32; ++p) s += g_ctx_part[(size_t)p * (NB * NC * LP) + i];
    int b = i / (NC * LP);
    int r = i % (NC * LP);
    int c = r / LP;
    int l = r % LP;
    g_ctx_t[((size_t)b * LP + l) * NC + c] = s;
}

// ---------------- kv stage A: warp-per-(b,which,o,l) dot over K=512 --------
__global__ void __launch_bounds__(256)
kv_a_kernel(const float* __restrict__ Wk1, const float* __restrict__ Wv) {
    const int wid  = threadIdx.x >> 5;
    const int lane = threadIdx.x & 31;
    const int gid  = blockIdx.x * 8 + wid;
    const int l = gid % LP;
    const int o = (gid / LP) % NO;
    const int which = (gid / (LP * NO)) & 1;
    const int b = gid / (LP * NO * 2);

    const float* Wrow = (which ? Wv : Wk1) + (size_t)o * NC;
    const float* crow = g_ctx_t + ((size_t)b * LP + l) * NC;

    float acc = 0.f;
#pragma unroll
    for (int i = 0; i < 4; ++i) {
        int k = lane * 4 + i * 128;
        float4 w4 = *(const float4*)(Wrow + k);
        float4 c4 = *(const float4*)(crow + k);
        acc += w4.x * c4.x + w4.y * c4.y + w4.z * c4.z + w4.w * c4.w;
    }
#pragma unroll
    for (int s = 16; s; s >>= 1) acc += __shfl_xor_sync(0xFFFFFFFFu, acc, s);

    if (lane == 0) {
        int sidx = which ? 4 : 2;
        float y = fmaxf(fmaf(acc, g_scale[sidx * NO + o], g_bias[sidx * NO + o]), 0.f);
        if (which == 0) g_k1[((size_t)b * LP + l) * NO + o] = y;   // [B][LP][O]
        else            g_val[((size_t)b * NO + o) * LP + l] = y;  // [B][O][LP]
    }
}

// ---------------- kv stage B: key = relu(BN(Wk2 @ k1)), warp-per-(b,o,l) ---
__global__ void __launch_bounds__(256)
kv_b_kernel(const float* __restrict__ Wk2) {
    const int wid  = threadIdx.x >> 5;
    const int lane = threadIdx.x & 31;
    const int gid  = blockIdx.x * 8 + wid;
    const int l = gid % LP;
    const int o = (gid / LP) % NO;
    const int b = gid / (LP * NO);

    const float* Wrow = Wk2 + (size_t)o * NO;
    const float* xrow = g_k1 + ((size_t)b * LP + l) * NO;

    float acc = 0.f;
#pragma unroll
    for (int i = 0; i < 2; ++i) {
        int k = lane * 4 + i * 128;
        float4 w4 = *(const float4*)(Wrow + k);
        float4 x4 = *(const float4*)(xrow + k);
        acc += w4.x * x4.x + w4.y * x4.y + w4.z * x4.z + w4.w * x4.w;
    }
#pragma unroll
    for (int s = 16; s; s >>= 1) acc += __shfl_xor_sync(0xFFFFFFFFu, acc, s);

    if (lane == 0) {
        float y = fmaxf(fmaf(acc, g_scale[3 * NO + o], g_bias[3 * NO + o]), 0.f);
        g_key[((size_t)b * NO + o) * LP + l] = y;
    }
}

// ================= bf16 mma.sync GEMM (2-term split, cp.async pipeline) ====
// CTA tile 128(m) x 128(n), K staged 32 per stage, 4-stage cp.async ring.
// 8 warps: 2(m) x 4(n); warp tile 64x32; mma.m16n8k16. 3 MMAs per frag pair:
// AhBh + AhBl + AlBh (AlBl dropped, <=2^-18 relative).
#define SA_STRIDE 80            // bytes per A smem row (32 bf16 + 8 pad)
#define SB_STRIDE 272           // bytes per B smem row (128 bf16 + 8 pad)
#define SA_BYTES  (128 * SA_STRIDE)           // 10240 per split
#define SB_BYTES  (32 * SB_STRIDE)            // 8704 per split
#define STAGE_BYTES (2 * SA_BYTES + 2 * SB_BYTES)  // 37888
#define NSTAGE 4
#define GEMM_SMEM (NSTAGE * STAGE_BYTES)      // 151552

__device__ __forceinline__ void load_stage(
    uint32_t sbase,
    const __nv_bfloat16* __restrict__ Wh, const __nv_bfloat16* __restrict__ Wl,
    const __nv_bfloat16* __restrict__ Xh, const __nv_bfloat16* __restrict__ Xl,
    int K, int m0, int n0, int kq, int t)
{
    // A: [128m x 32k] bf16, rows padded to 80B. 512 chunks of 16B per split.
#pragma unroll
    for (int i = 0; i < 2; ++i) {
        int f = t + i * 256;
        int m = f >> 2, j = f & 3;
        size_t src = (size_t)(m0 + m) * K + kq + j * 8;
        uint32_t dst = sbase + m * SA_STRIDE + j * 16;
        cpa16(dst, Wh + src);
        cpa16(dst + SA_BYTES, Wl + src);
    }
    // B: [32k x 128n] bf16, rows padded to 272B. 512 chunks per split.
#pragma unroll
    for (int i = 0; i < 2; ++i) {
        int f = t + i * 256;
        int k = f >> 4, j = f & 15;
        size_t src = (size_t)(kq + k) * NHW + n0 + j * 8;
        uint32_t dst = sbase + 2 * SA_BYTES + k * SB_STRIDE + j * 16;
        cpa16(dst, Xh + src);
        cpa16(dst + SB_BYTES, Xl + src);
    }
}

__global__ void __launch_bounds__(256, 1)
gemm_bf16(float* __restrict__ Yext, int pass)
{
    extern __shared__ char dsm[];
    const int t    = threadIdx.x;
    const int wid  = t >> 5;
    const int lane = t & 31;
    const int b    = blockIdx.z;
    const int m0   = blockIdx.y * 128;
    const int n0   = blockIdx.x * 128;

    const int K = pass ? NO : NC;
    const __nv_bfloat16* Wh = pass ? g_w2h : g_w1h;
    const __nv_bfloat16* Wl = pass ? g_w2l : g_w1l;
    const __nv_bfloat16* Xh = (pass ? g_q1h : g_xh) + (size_t)b * K * NHW;
    const __nv_bfloat16* Xl = (pass ? g_q1l : g_xl) + (size_t)b * K * NHW;
    const int sidx = pass ? 1 : 0;

    const uint32_t sb = smem_u32(dsm);
    const int warp_m = (wid & 1) * 64;
    const int warp_n = (wid >> 1) * 32;

    float acc[4][4][4];
#pragma unroll
    for (int i = 0; i < 4; ++i)
#pragma unroll
        for (int j = 0; j < 4; ++j)
#pragma unroll
            for (int e = 0; e < 4; ++e) acc[i][j][e] = 0.f;

    const int S = K >> 5;  // 16 or 8 stages

    // prologue: prefetch NSTAGE-1 stages
#pragma unroll
    for (int s = 0; s < NSTAGE - 1; ++s) {
        load_stage(sb + s * STAGE_BYTES, Wh, Wl, Xh, Xl, K, m0, n0, s * 32, t);
        CP_COMMIT();
    }

#pragma unroll 1
    for (int s = 0; s < S; ++s) {
        CP_WAIT2();          // stage s copy complete (<=2 groups pending)
        __syncthreads();     // visibility of all threads' copies + buffer reuse guard

        const int sn = s + NSTAGE - 1;
        if (sn < S)
            load_stage(sb + (sn % NSTAGE) * STAGE_BYTES, Wh, Wl, Xh, Xl, K, m0, n0, sn * 32, t);
        CP_COMMIT();

        const uint32_t bufA = sb + (s % NSTAGE) * STAGE_BYTES;
        const uint32_t bufB = bufA + 2 * SA_BYTES;

#pragma unroll
        for (int kk = 0; kk < 2; ++kk) {           // two k16 steps per stage
            uint32_t ah[4][4], al[4][4];
#pragma unroll
            for (int i = 0; i < 4; ++i) {
                uint32_t ad = bufA + (warp_m + 16 * i + (lane & 15)) * SA_STRIDE
                            + kk * 32 + (lane >> 4) * 16;
                ldsm4(ah[i], ad);
                ldsm4(al[i], ad + SA_BYTES);
            }
            uint32_t bh[2][4], bl[2][4];
#pragma unroll
            for (int jj = 0; jj < 2; ++jj) {
                uint32_t ad = bufB + (kk * 16 + (lane & 15)) * SB_STRIDE
                            + (warp_n + jj * 16 + (lane >> 4) * 8) * 2;
                ldsm4t(bh[jj], ad);
                ldsm4t(bl[jj], ad + SB_BYTES);
            }
#pragma unroll
            for (int i = 0; i < 4; ++i)
#pragma unroll
                for (int j = 0; j < 4; ++j) {
                    const int jj = j >> 1, r = (j & 1) * 2;
                    mma_bf16(acc[i][j], ah[i], bh[jj][r], bh[jj][r + 1]);
                    mma_bf16(acc[i][j], ah[i], bl[jj][r], bl[jj][r + 1]);
                    mma_bf16(acc[i][j], al[i], bh[jj][r], bh[jj][r + 1]);
                }
        }
    }

    // epilogue: BN + relu, then store (pass0: bf16 split -> q1; pass1: fp32 -> Y)
#pragma unroll
    for (int i = 0; i < 4; ++i) {
        const int rg = m0 + warp_m + 16 * i + (lane >> 2);
        const float sc0 = g_scale[sidx * NO + rg],     bi0 = g_bias[sidx * NO + rg];
        const float sc1 = g_scale[sidx * NO + rg + 8], bi1 = g_bias[sidx * NO + rg + 8];
#pragma unroll
        for (int j = 0; j < 4; ++j) {
            const int cg = n0 + warp_n + 8 * j + (lane & 3) * 2;
            float y00 = fmaxf(fmaf(acc[i][j][0], sc0, bi0), 0.f);
            float y01 = fmaxf(fmaf(acc[i][j][1], sc0, bi0), 0.f);
            float y10 = fmaxf(fmaf(acc[i][j][2], sc1, bi1), 0.f);
            float y11 = fmaxf(fmaf(acc[i][j][3], sc1, bi1), 0.f);
            if (pass) {
                float* Yb = Yext + (size_t)b * NO * NHW;
                *(float2*)(Yb + (size_t)rg * NHW + cg)       = make_float2(y00, y01);
                *(float2*)(Yb + (size_t)(rg + 8) * NHW + cg) = make_float2(y10, y11);
            } else {
                const size_t base = (size_t)b * NO * NHW;
                __nv_bfloat162 h2, l2;
                // row rg
                h2.x = __float2bfloat16(y00);
                h2.y = __float2bfloat16(y01);
                l2.x = __float2bfloat16(y00 - __bfloat162float(h2.x));
                l2.y = __float2bfloat16(y01 - __bfloat162float(h2.y));
                *(__nv_bfloat162*)(g_q1h + base + (size_t)rg * NHW + cg) = h2;
                *(__nv_bfloat162*)(g_q1l + base + (size_t)rg * NHW + cg) = l2;
                // row rg+8
                h2.x = __float2bfloat16(y10);
                h2.y = __float2bfloat16(y11);
                l2.x = __float2bfloat16(y10 - __bfloat162float(h2.x));
                l2.y = __float2bfloat16(y11 - __bfloat162float(h2.y));
                *(__nv_bfloat162*)(g_q1h + base + (size_t)(rg + 8) * NHW + cg) = h2;
                *(__nv_bfloat162*)(g_q1l + base + (size_t)(rg + 8) * NHW + cg) = l2;
            }
        }
    }
}

// ---------------- attention: per-pixel softmax over L=19 -------------------
__global__ void __launch_bounds__(256)
attention_kernel(float* qout) {
    __shared__ float key_s[NO * LP];
    __shared__ float val_s[NO * LP];

    const int b = blockIdx.y;
    const int t = threadIdx.x;
    const int n = blockIdx.x * 256 + t;

    for (int e = t; e < NO * LP; e += 256) {
        key_s[e] = g_key[(size_t)b * NO * LP + e];
        val_s[e] = g_val[(size_t)b * NO * LP + e];
    }
    __syncthreads();

    float s[LP];
#pragma unroll
    for (int l = 0; l < LP; ++l) s[l] = 0.f;

    float* qb = qout + (size_t)b * NO * NHW + n;
#pragma unroll 4
    for (int o = 0; o < NO; ++o) {
        float qv = qb[(size_t)o * NHW];
#pragma unroll
        for (int j = 0; j < 5; ++j) {
            float4 k4 = *(const float4*)&key_s[o * LP + j * 4];
            s[j * 4 + 0] = fmaf(qv, k4.x, s[j * 4 + 0]);
            s[j * 4 + 1] = fmaf(qv, k4.y, s[j * 4 + 1]);
            s[j * 4 + 2] = fmaf(qv, k4.z, s[j * 4 + 2]);
            s[j * 4 + 3] = fmaf(qv, k4.w, s[j * 4 + 3]);
        }
    }

    float mx = -1e30f;
#pragma unroll
    for (int l = 0; l < NL; ++l) {
        s[l] *= 0.0625f;                   // 1/sqrt(256)
        mx = fmaxf(mx, s[l]);
    }
    float sum = 0.f;
#pragma unroll
    for (int l = 0; l < NL; ++l) {
        s[l] = __expf(s[l] - mx);
        sum += s[l];
    }
    float inv = 1.f / sum;
#pragma unroll
    for (int l = 0; l < NL; ++l) s[l] *= inv;
    s[19] = 0.f;

#pragma unroll 4
    for (int o = 0; o < NO; ++o) {
        float acc = 0.f;
#pragma unroll
        for (int j = 0; j < 5; ++j) {
            float4 v4 = *(const float4*)&val_s[o * LP + j * 4];
            acc = fmaf(s[j * 4 + 0], v4.x, acc);
            acc = fmaf(s[j * 4 + 1], v4.y, acc);
            acc = fmaf(s[j * 4 + 2], v4.z, acc);
            acc = fmaf(s[j * 4 + 3], v4.w, acc);
        }
        qb[(size_t)o * NHW] = acc;
    }
}

// ---------------- launch ---------------------------------------------------
extern "C" void kernel_launch(void* const* d_in, const int* in_sizes, int n_in,
                              void* d_out, int out_size) {
    const float* tfeat = (const float*)d_in[0];
    const float* sfeat = (const float*)d_in[1];
    const float* taux  = (const float*)d_in[2];
    const float* Wq1  = (const float*)d_in[4];
    const float* bnq1 = (const float*)d_in[5];
    const float* Wq2  = (const float*)d_in[6];
    const float* bnq2 = (const float*)d_in[7];
    const float* Wk1  = (const float*)d_in[8];
    const float* bnk1 = (const float*)d_in[9];
    const float* Wk2  = (const float*)d_in[10];
    const float* bnk2 = (const float*)d_in[11];
    const float* Wv   = (const float*)d_in[12];
    const float* bnv  = (const float*)d_in[13];
    float* out = (float*)d_out;

    cudaFuncSetAttribute(gemm_bf16, cudaFuncAttributeMaxDynamicSharedMemorySize, GEMM_SMEM);

    // 1. fold BN params + bf16 splits of W and X
    prep_kernel<<<5, 256>>>(bnq1, bnq2, bnk1, bnk2, bnv);
    wsplit_kernel<<<(NO * NC + NO * NO + 255) / 256, 256>>>(Wq1, Wq2);
    xsplit_kernel<<<(NB * NC * NHW / 4 + 255) / 256, 256>>>(tfeat);

    // 2. context = aux^T @ source feats (partials), then reduce+transpose
    context_kernel<<<dim3(HSPLIT, NC / CTILE, NB), 256>>>(sfeat, taux);
    ctx_reduce_kernel<<<(NB * NC * LP + 255) / 256, 256>>>();

    // 3. key / value small convs (warp-per-output)
    kv_a_kernel<<<NB * 2 * NO * LP / 8, 256>>>(Wk1, Wv);
    kv_b_kernel<<<NB * NO * LP / 8, 256>>>(Wk2);

    // 4. query GEMMs on tensor cores (bf16 2-term split via mma.sync)
    gemm_bf16<<<dim3(NHW / 128, 2, NB), 256, GEMM_SMEM>>>(out, 0);  // -> q1 (bf16 split)
    gemm_bf16<<<dim3(NHW / 128, 2, NB), 256, GEMM_SMEM>>>(out, 1);  // -> d_out fp32

    // 5. attention (in place on d_out)
    attention_kernel<<<dim3(NHW / 256, NB), 256>>>(out);
}